// round 15
// baseline (speedup 1.0000x reference)
#include <cuda_runtime.h>
#include <math.h>

// Problem constants
#define B_    32
#define C_    256
#define L_    8192
#define H_    16
#define ROWS  (B_ * C_)          // 8192
#define L4    (L_ / 4)           // 2048 float4 per row
#define ITER  8
#define TPB   256

// 1-row tasks. mean-stream: per batch [256 means, 1 excite] = 8224;
// scale-stream: 8192.
#define NM    (B_ * (C_ + 1))    // 8224
#define NS    ROWS               // 8192
#define NTASKS (NM + NS)         // 16416
// Constraints (validated across R7/R10-R13):
//  margin = gap - frontier >= ~300, frontier = 2*888 = 1776 (prefetch D=2)
//  window_x = (gap/2)*32KB <= ~35MB  => gap <= ~2300
// LEAD=1300: gap = 2087-2b -> margin ~280-310, window ~33MB. Both hold.
#define LEAD  1300
#define ALT_END (LEAD + 2 * (NM - LEAD))   // 15148
#define P_BLOCKS 888

// Scratch (allocation-free rule: __device__ globals)
__device__ float d_y[ROWS];
__device__ float d_g[ROWS];
__device__ int   g_task;
__device__ int   g_cnt[B_];
__device__ int   g_flag[B_];

// ---------------------------------------------------------------------------
__global__ void se_init() {
    const int t = threadIdx.x;
    if (t == 0) g_task = 0;
    if (t < B_) { g_cnt[t] = 0; g_flag[t] = 0; }
}

// ---------------------------------------------------------------------------
// Persistent worker. Dynamic in-order queue with ONE-deep task-id prefetch
// (dispatch atomic overlaps the previous task's memory work).
// ---------------------------------------------------------------------------
__global__ __launch_bounds__(TPB, 6) void se_persist(const float4* __restrict__ x,
                                                     float4* __restrict__ out,
                                                     const float* __restrict__ W1,
                                                     const float* __restrict__ W2) {
    __shared__ int   s_task[2];
    __shared__ float warp_sums[8];
    __shared__ float ys[C_];
    __shared__ float hs[H_];

    const int t    = threadIdx.x;
    const int lane = t & 31;
    const int wid  = t >> 5;

    if (t == 0) s_task[0] = atomicAdd(&g_task, 1);
    __syncthreads();

    int parity = 0;
    for (;;) {
        const int task = s_task[parity];
        if (task >= NTASKS) return;
        if (t == 0) s_task[parity ^ 1] = atomicAdd(&g_task, 1);  // prefetch next

        // ---- queue position -> (stream, index) ----
        int mean_idx = -1, scale_idx = -1;
        if (task < LEAD) {
            mean_idx = task;
        } else if (task < ALT_END) {
            const int j = task - LEAD;
            if (j & 1) mean_idx = LEAD + (j >> 1);
            else       scale_idx = j >> 1;
        } else {
            scale_idx = (NM - LEAD) + (task - ALT_END);
        }

        if (mean_idx >= 0) {
            const int b = mean_idx / (C_ + 1);
            const int r = mean_idx - b * (C_ + 1);
            if (r < C_) {
                // ---- MEAN of row (b, r): default policy -> L2 resident ----
                const int row = b * C_ + r;
                const float4* __restrict__ p = x + (size_t)row * L4;
                float s = 0.0f;
                #pragma unroll
                for (int i = 0; i < ITER; ++i) {
                    float4 v = __ldg(p + t + i * 256);
                    s += (v.x + v.y) + (v.z + v.w);
                }
                #pragma unroll
                for (int off = 16; off > 0; off >>= 1)
                    s += __shfl_xor_sync(0xFFFFFFFFu, s, off);
                if (lane == 0) warp_sums[wid] = s;
                __syncthreads();
                if (wid == 0) {
                    float tt = (lane < 8) ? warp_sums[lane] : 0.0f;
                    #pragma unroll
                    for (int off = 4; off > 0; off >>= 1)
                        tt += __shfl_xor_sync(0xFFFFFFFFu, tt, off);
                    if (lane == 0) {
                        d_y[row] = tt * (1.0f / (float)L_);
                        __threadfence();                    // release d_y
                        atomicAdd(&g_cnt[b], 1);
                    }
                }
            } else {
                // ---- EXCITE for batch b (waits only on trailing means) ----
                if (t == 0) {
                    while (((volatile int*)g_cnt)[b] < C_) __nanosleep(32);
                }
                __syncthreads();
                __threadfence();                            // acquire
                ys[t] = __ldcg(&d_y[b * C_ + t]);
                __syncthreads();
                {
                    const int hh = t >> 4;
                    const int k  = t & 15;
                    const float* __restrict__ w1 = W1 + hh * C_ + k * 16;
                    const float* __restrict__ yy = ys + k * 16;
                    float s = 0.0f;
                    #pragma unroll
                    for (int i = 0; i < 16; ++i) s += yy[i] * w1[i];
                    #pragma unroll
                    for (int off = 8; off > 0; off >>= 1)
                        s += __shfl_down_sync(0xFFFFFFFFu, s, off, 16);
                    if (k == 0) hs[hh] = fmaxf(s, 0.0f);
                }
                __syncthreads();
                {
                    float s = 0.0f;
                    const float* __restrict__ w2 = W2 + t * H_;
                    #pragma unroll
                    for (int j = 0; j < H_; ++j) s += hs[j] * w2[j];
                    d_g[b * C_ + t] = 1.0f / (1.0f + expf(-s));
                }
                __threadfence();                            // release d_g
                __syncthreads();
                if (t == 0) atomicExch(&g_flag[b], 1);
            }
        } else {
            // ---- SCALE row: __ldcs (L2 hit expected) * gate -> __stcs ----
            const int row = scale_idx;
            const int b   = row >> 8;
            if (t == 0) {
                while (((volatile int*)g_flag)[b] == 0) __nanosleep(32);
            }
            __syncthreads();
            __threadfence();                                // acquire
            const float gv = __ldcg(&d_g[row]);

            const float4* __restrict__ px = x   + (size_t)row * L4 + t;
            float4* __restrict__       po = out + (size_t)row * L4 + t;
            #pragma unroll
            for (int g2 = 0; g2 < 2; ++g2) {
                float4 v[4];
                #pragma unroll
                for (int i = 0; i < 4; ++i)
                    v[i] = __ldcs(px + (g2 * 4 + i) * 256);
                #pragma unroll
                for (int i = 0; i < 4; ++i) {
                    v[i].x *= gv; v[i].y *= gv; v[i].z *= gv; v[i].w *= gv;
                    __stcs(po + (g2 * 4 + i) * 256, v[i]);
                }
            }
        }
        __syncthreads();   // smem reuse + prefetched id visibility
        parity ^= 1;
    }
}

// ---------------------------------------------------------------------------
extern "C" void kernel_launch(void* const* d_in, const int* in_sizes, int n_in,
                              void* d_out, int out_size) {
    const float4* x  = (const float4*)d_in[0];
    const float*  W1 = (const float*)d_in[1];
    const float*  W2 = (const float*)d_in[2];
    float4* out = (float4*)d_out;

    se_init<<<1, 64>>>();
    se_persist<<<P_BLOCKS, TPB>>>(x, out, W1, W2);
}

// round 16
// speedup vs baseline: 1.0338x; 1.0338x over previous
#include <cuda_runtime.h>
#include <math.h>

// Problem constants
#define B_    32
#define C_    256
#define L_    8192
#define H_    16
#define ROWS  (B_ * C_)          // 8192
#define L4    (L_ / 4)           // 2048 float4 per row
#define ITER  8
#define TPB   256

// R7 geometry (proven best: 105.4us, 494MB traffic).
// mean-stream: per batch [256 means, 1 excite] = 8224; scale-stream: 8192.
// D=1 in-flight: frontier=888. gap=2*LEAD-513-2b=1543-2b -> margin ~655.
// window = (gap/2)*32KB ~ 24.6MB <= ~28MB L2 reuse cap.
#define NM    (B_ * (C_ + 1))    // 8224
#define NS    ROWS               // 8192
#define NTASKS (NM + NS)         // 16416
#define LEAD  1028
#define ALT_END (LEAD + 2 * (NM - LEAD))   // 15420
#define P_BLOCKS 888

// Scratch (allocation-free rule: __device__ globals)
__device__ float d_y[ROWS];
__device__ float d_g[ROWS];
__device__ int   g_task;
__device__ int   g_cnt[B_];
__device__ int   g_flag[B_];

// ---------------------------------------------------------------------------
__global__ void se_init() {
    const int t = threadIdx.x;
    if (t == 0) g_task = 0;
    if (t < B_) { g_cnt[t] = 0; g_flag[t] = 0; }
}

// ---------------------------------------------------------------------------
// Persistent worker. Dynamic IN-ORDER queue, ONE task in flight per block
// (grab -> finish -> grab). The grab order is a completion frontier that
// regulates dependency readiness AND L2 reuse distance. Perturbations that
// failed: prefetch D=2 (R8/R13/R14: margin/window infeasible), static RR
// (R9: drift), fat tasks (R10/R11: window blowout). Do not repeat them.
// Dependency waits use ALL-THREAD __ldcg polls (no t0-spin, no barrier):
// same-address poll is 1 L2 request per warp; warps decouple at task start.
// ---------------------------------------------------------------------------
__global__ __launch_bounds__(TPB, 6) void se_persist(const float4* __restrict__ x,
                                                     float4* __restrict__ out,
                                                     const float* __restrict__ W1,
                                                     const float* __restrict__ W2) {
    __shared__ int   s_task;
    __shared__ float warp_sums[8];
    __shared__ float ys[C_];
    __shared__ float hs[H_];

    const int t    = threadIdx.x;
    const int lane = t & 31;
    const int wid  = t >> 5;

    for (;;) {
        if (t == 0) s_task = atomicAdd(&g_task, 1);
        __syncthreads();
        const int task = s_task;
        if (task >= NTASKS) return;

        // ---- queue position -> (stream, index) ----
        int mean_idx = -1, scale_idx = -1;
        if (task < LEAD) {
            mean_idx = task;
        } else if (task < ALT_END) {
            const int j = task - LEAD;
            if (j & 1) mean_idx = LEAD + (j >> 1);
            else       scale_idx = j >> 1;
        } else {
            scale_idx = (NM - LEAD) + (task - ALT_END);
        }

        if (mean_idx >= 0) {
            const int b = mean_idx / (C_ + 1);
            const int r = mean_idx - b * (C_ + 1);
            if (r < C_) {
                // ---- MEAN of row (b, r): default policy -> L2 resident ----
                const int row = b * C_ + r;
                const float4* __restrict__ p = x + (size_t)row * L4;
                float s = 0.0f;
                #pragma unroll
                for (int i = 0; i < ITER; ++i) {
                    float4 v = __ldg(p + t + i * 256);
                    s += (v.x + v.y) + (v.z + v.w);
                }
                #pragma unroll
                for (int off = 16; off > 0; off >>= 1)
                    s += __shfl_xor_sync(0xFFFFFFFFu, s, off);
                if (lane == 0) warp_sums[wid] = s;
                __syncthreads();
                if (wid == 0) {
                    float tt = (lane < 8) ? warp_sums[lane] : 0.0f;
                    #pragma unroll
                    for (int off = 4; off > 0; off >>= 1)
                        tt += __shfl_xor_sync(0xFFFFFFFFu, tt, off);
                    if (lane == 0) {
                        d_y[row] = tt * (1.0f / (float)L_);
                        __threadfence();                    // release d_y
                        atomicAdd(&g_cnt[b], 1);
                    }
                }
            } else {
                // ---- EXCITE for batch b: all threads poll cnt (no barrier) --
                while (__ldcg(&g_cnt[b]) < C_) __nanosleep(32);
                __threadfence();                            // acquire
                ys[t] = __ldcg(&d_y[b * C_ + t]);
                __syncthreads();
                {
                    const int hh = t >> 4;
                    const int k  = t & 15;
                    const float* __restrict__ w1 = W1 + hh * C_ + k * 16;
                    const float* __restrict__ yy = ys + k * 16;
                    float s = 0.0f;
                    #pragma unroll
                    for (int i = 0; i < 16; ++i) s += yy[i] * w1[i];
                    #pragma unroll
                    for (int off = 8; off > 0; off >>= 1)
                        s += __shfl_down_sync(0xFFFFFFFFu, s, off, 16);
                    if (k == 0) hs[hh] = fmaxf(s, 0.0f);
                }
                __syncthreads();
                {
                    float s = 0.0f;
                    const float* __restrict__ w2 = W2 + t * H_;
                    #pragma unroll
                    for (int j = 0; j < H_; ++j) s += hs[j] * w2[j];
                    d_g[b * C_ + t] = 1.0f / (1.0f + expf(-s));
                }
                __threadfence();                            // release d_g
                __syncthreads();
                if (t == 0) atomicExch(&g_flag[b], 1);
            }
        } else {
            // ---- SCALE row: all threads poll flag (no barrier, no t0 spin),
            // then stream: __ldcs (L2 hit expected) * gate -> __stcs.
            const int row = scale_idx;
            const int b   = row >> 8;
            while (__ldcg(&g_flag[b]) == 0) __nanosleep(32);
            __threadfence();                                // acquire
            const float gv = __ldcg(&d_g[row]);

            const float4* __restrict__ px = x   + (size_t)row * L4 + t;
            float4* __restrict__       po = out + (size_t)row * L4 + t;
            #pragma unroll
            for (int g2 = 0; g2 < 2; ++g2) {
                float4 v[4];
                #pragma unroll
                for (int i = 0; i < 4; ++i)
                    v[i] = __ldcs(px + (g2 * 4 + i) * 256);
                #pragma unroll
                for (int i = 0; i < 4; ++i) {
                    v[i].x *= gv; v[i].y *= gv; v[i].z *= gv; v[i].w *= gv;
                    __stcs(po + (g2 * 4 + i) * 256, v[i]);
                }
            }
        }
        __syncthreads();   // s_task / smem reuse safety before next grab
    }
}

// ---------------------------------------------------------------------------
extern "C" void kernel_launch(void* const* d_in, const int* in_sizes, int n_in,
                              void* d_out, int out_size) {
    const float4* x  = (const float4*)d_in[0];
    const float*  W1 = (const float*)d_in[1];
    const float*  W2 = (const float*)d_in[2];
    float4* out = (float4*)d_out;

    se_init<<<1, 64>>>();
    se_persist<<<P_BLOCKS, TPB>>>(x, out, W1, W2);
}

// round 17
// speedup vs baseline: 1.1365x; 1.0993x over previous
#include <cuda_runtime.h>
#include <math.h>

// Problem constants
#define B_    32
#define C_    256
#define L_    8192
#define H_    16
#define ROWS  (B_ * C_)          // 8192
#define L4    (L_ / 4)           // 2048 float4 per row
#define ITER  8
#define TPB   256

// Streams: mean-stream = per batch [256 means, 1 excite] = 257*32 = 8224
//          scale-stream = 256*32 = 8192
#define NM    (B_ * (C_ + 1))    // 8224
#define NS    ROWS               // 8192
#define NTASKS (NM + NS)         // 16416
#define LEAD  1028               // 4 batches of mean-stream first
#define ALT_END (LEAD + 2 * (NM - LEAD))   // 15420
#define P_BLOCKS 888

// Scratch (allocation-free rule: __device__ globals)
__device__ float d_y[ROWS];
__device__ float d_g[ROWS];
__device__ int   g_task;
__device__ int   g_cnt[B_];
__device__ int   g_flag[B_];

// ---------------------------------------------------------------------------
__global__ void se_init() {
    const int t = threadIdx.x;
    if (t == 0) g_task = 0;
    if (t < B_) { g_cnt[t] = 0; g_flag[t] = 0; }
}

// ---------------------------------------------------------------------------
// Persistent worker: dynamic IN-ORDER atomic queue, ONE task in flight per
// block (grab -> finish -> grab). The grab order doubles as a completion
// frontier: any task >=888 positions back is provably finished when a new
// task is grabbed, which (a) guarantees dependencies are ready (margin ~655)
// and (b) bounds the mean->scale L2 reuse window to ~25MB (under the ~28MB
// effective cap). Probed-and-regressed variants: id prefetch (R8/R13/R14),
// static round-robin (R9), 2-row tasks (R10/R11), pair grab (R12),
// barrier-free polls (R15). This configuration is the measured optimum.
// ---------------------------------------------------------------------------
__global__ __launch_bounds__(TPB, 6) void se_persist(const float4* __restrict__ x,
                                                     float4* __restrict__ out,
                                                     const float* __restrict__ W1,
                                                     const float* __restrict__ W2) {
    __shared__ int   s_task;
    __shared__ float warp_sums[8];
    __shared__ float ys[C_];
    __shared__ float hs[H_];

    const int t    = threadIdx.x;
    const int lane = t & 31;
    const int wid  = t >> 5;

    for (;;) {
        if (t == 0) s_task = atomicAdd(&g_task, 1);
        __syncthreads();
        const int task = s_task;
        if (task >= NTASKS) return;

        // ---- map queue position -> (stream, index) ----
        int mean_idx = -1, scale_idx = -1;
        if (task < LEAD) {
            mean_idx = task;
        } else if (task < ALT_END) {
            const int j = task - LEAD;
            if (j & 1) mean_idx = LEAD + (j >> 1);
            else       scale_idx = j >> 1;
        } else {
            scale_idx = (NM - LEAD) + (task - ALT_END);
        }

        if (mean_idx >= 0) {
            const int b = mean_idx / (C_ + 1);
            const int r = mean_idx - b * (C_ + 1);
            if (r < C_) {
                // ---- MEAN of row (b, r): default policy -> L2 resident ----
                const int row = b * C_ + r;
                const float4* __restrict__ p = x + (size_t)row * L4;
                float s = 0.0f;
                #pragma unroll
                for (int i = 0; i < ITER; ++i) {
                    float4 v = __ldg(p + t + i * 256);
                    s += (v.x + v.y) + (v.z + v.w);
                }
                #pragma unroll
                for (int off = 16; off > 0; off >>= 1)
                    s += __shfl_xor_sync(0xFFFFFFFFu, s, off);
                if (lane == 0) warp_sums[wid] = s;
                __syncthreads();
                if (wid == 0) {
                    float tt = (lane < 8) ? warp_sums[lane] : 0.0f;
                    #pragma unroll
                    for (int off = 4; off > 0; off >>= 1)
                        tt += __shfl_xor_sync(0xFFFFFFFFu, tt, off);
                    if (lane == 0) {
                        d_y[row] = tt * (1.0f / (float)L_);
                        __threadfence();                    // release d_y
                        atomicAdd(&g_cnt[b], 1);
                    }
                }
            } else {
                // ---- EXCITE for batch b (spins only on trailing in-flight means)
                if (t == 0) {
                    while (((volatile int*)g_cnt)[b] < C_) __nanosleep(32);
                }
                __syncthreads();
                __threadfence();                            // acquire
                ys[t] = __ldcg(&d_y[b * C_ + t]);
                __syncthreads();
                {
                    const int hh = t >> 4;
                    const int k  = t & 15;
                    const float* __restrict__ w1 = W1 + hh * C_ + k * 16;
                    const float* __restrict__ yy = ys + k * 16;
                    float s = 0.0f;
                    #pragma unroll
                    for (int i = 0; i < 16; ++i) s += yy[i] * w1[i];
                    #pragma unroll
                    for (int off = 8; off > 0; off >>= 1)
                        s += __shfl_down_sync(0xFFFFFFFFu, s, off, 16);
                    if (k == 0) hs[hh] = fmaxf(s, 0.0f);
                }
                __syncthreads();
                {
                    float s = 0.0f;
                    const float* __restrict__ w2 = W2 + t * H_;
                    #pragma unroll
                    for (int j = 0; j < H_; ++j) s += hs[j] * w2[j];
                    d_g[b * C_ + t] = 1.0f / (1.0f + expf(-s));
                }
                __threadfence();                            // release d_g
                __syncthreads();
                if (t == 0) atomicExch(&g_flag[b], 1);
            }
        } else {
            // ---- SCALE row: excite completed ~1400 queue slots earlier ----
            const int row = scale_idx;
            const int b   = row >> 8;
            if (t == 0) {
                while (((volatile int*)g_flag)[b] == 0) __nanosleep(32);
            }
            __syncthreads();
            __threadfence();                                // acquire
            const float gv = __ldcg(&d_g[row]);

            const float4* __restrict__ px = x   + (size_t)row * L4 + t;
            float4* __restrict__       po = out + (size_t)row * L4 + t;
            #pragma unroll
            for (int g2 = 0; g2 < 2; ++g2) {
                float4 v[4];
                #pragma unroll
                for (int i = 0; i < 4; ++i)
                    v[i] = __ldcs(px + (g2 * 4 + i) * 256);
                #pragma unroll
                for (int i = 0; i < 4; ++i) {
                    v[i].x *= gv; v[i].y *= gv; v[i].z *= gv; v[i].w *= gv;
                    __stcs(po + (g2 * 4 + i) * 256, v[i]);
                }
            }
        }
        __syncthreads();   // smem reuse safety + next task id visibility
    }
}

// ---------------------------------------------------------------------------
extern "C" void kernel_launch(void* const* d_in, const int* in_sizes, int n_in,
                              void* d_out, int out_size) {
    const float4* x  = (const float4*)d_in[0];
    const float*  W1 = (const float*)d_in[1];
    const float*  W2 = (const float*)d_in[2];
    float4* out = (float4*)d_out;

    se_init<<<1, 64>>>();
    se_persist<<<P_BLOCKS, TPB>>>(x, out, W1, W2);
}